// round 10
// baseline (speedup 1.0000x reference)
#include <cuda_runtime.h>
#include <cstdint>
#include <math.h>

#define N 8192
#define E 262144
#define NW 256              // bitmap words per row (8192 bits / 32)
#define LISTCAP 256         // max union degree; Poisson(~64) tail @256 ~ 0
#define GEMM_BLOCKS 128     // 64 rows per block
#define SB_BLOCKS 512       // setbits: 2 edges per thread
#define EM_BLOCKS 128       // edge_max: 2048 edges per block (smem-staged)

// ---------------- scratch (device globals; zero-initialized at module load) --
__device__ __align__(16) float          g_h[N * 64];
__device__ __align__(16) float          g_ht[N * 64];
__device__ __align__(16) float          g_asrc[N];
__device__ __align__(16) float          g_adst[N];
__device__ __align__(16) float          g_Ssum[64];
__device__ __align__(16) float          g_part[GEMM_BLOCKS * 64];
__device__ unsigned                     g_fillbits;
__device__ __align__(16) unsigned       g_bf[N * NW];     // cleared by k_build after use
__device__ __align__(16) unsigned       g_br[N * NW];     // cleared by k_build after use
__device__ __align__(16) unsigned short g_nbr[N * LISTCAP];  // per-row union list
__device__ __align__(16) int            g_cnt[N];

// ---------------- helpers ----------------
__device__ __forceinline__ float eluf(float x)  { return x > 0.f ? x : expf(x) - 1.f; }
__device__ __forceinline__ float lrelu(float x) { return x > 0.f ? x : 0.2f * x; }
__device__ __forceinline__ unsigned fmap(float f) {
    unsigned u = __float_as_uint(f);
    return (u & 0x80000000u) ? ~u : (u | 0x80000000u);
}
__device__ __forceinline__ float funmap(unsigned u) {
    return (u & 0x80000000u) ? __uint_as_float(u & 0x7fffffffu) : __uint_as_float(~u);
}

// ---------------- kernels ----------------
// set adjacency bits; threads with gid < N also compute symbolic features.
// edge_index is int32 (JAX downcasts int64 without x64 mode).
__global__ void k_setbits_feat(const int* __restrict__ ei,
                               const float* __restrict__ x,
                               const float* __restrict__ symW,
                               const float* __restrict__ symb) {
    int gid = blockIdx.x * blockDim.x + threadIdx.x;
    int k0 = gid * 2;
    if (k0 < E) {
        int2 r2 = *(const int2*)(ei + k0);
        int2 c2 = *(const int2*)(ei + E + k0);
        if ((unsigned)r2.x < N && (unsigned)c2.x < N && r2.x != c2.x) {
            atomicOr(&g_bf[(r2.x << 8) + (c2.x >> 5)], 1u << (c2.x & 31));
            atomicOr(&g_br[(c2.x << 8) + (r2.x >> 5)], 1u << (r2.x & 31));
        }
        if ((unsigned)r2.y < N && (unsigned)c2.y < N && r2.y != c2.y) {
            atomicOr(&g_bf[(r2.y << 8) + (c2.y >> 5)], 1u << (c2.y & 31));
            atomicOr(&g_br[(c2.y << 8) + (r2.y >> 5)], 1u << (r2.y & 31));
        }
    }

    int i = gid;
    if (i >= N) return;
    const float* xr = x + i * 16;
    float am = xr[0], bod = xr[1], dox = xr[2], ph = xr[4], ni = xr[7];

    float p_ph  = ph  < 6.5f   ? (6.5f - ph) / 6.5f     : (ph  > 8.5f ? (ph  - 8.5f) / 8.5f : 0.f);
    float p_am  = am  < 0.001f ? (0.001f - am) / 0.001f : (am  > 0.5f ? (am  - 0.5f) / 0.5f : 0.f);
    float p_bod = bod < 0.001f ? (0.001f - bod) / 0.001f: (bod > 5.0f ? (bod - 5.0f) / 5.0f : 0.f);
    float p_do  = dox < 6.0f   ? (6.0f - dox) / 6.0f    : 0.f;
    float p_ni  = ni  < 0.001f ? (0.001f - ni) / 0.001f : (ni  > 10.f ? (ni  - 10.f) / 10.f : 0.f);

    float bact = (1.2f * am / 0.5f + 1.5f * bod / 5.0f - 0.8f * dox / 10.0f) * (1.f / 3.f);
    float chem = (1.5f * ph / 8.5f + ni / 10.0f) * 0.5f;
    float org  = (2.0f * bod / 5.0f - 1.5f * dox / 10.0f + 0.8f * am / 0.5f) * (1.f / 3.f);
    float agri = 2.0f * ni / 10.0f;
    float comp = 1.f / (1.f + (p_ph + p_am + p_bod + p_do + p_ni) + 1e-8f);

    float f[10] = { p_ph, p_am, p_bod, p_do, p_ni, bact, chem, org, agri, comp };
    float* hr = g_h + i * 64;
#pragma unroll
    for (int k = 0; k < 16; k++) hr[k] = xr[k];
    for (int j = 0; j < 32; j++) {
        float s = symb[j];
#pragma unroll
        for (int k = 0; k < 10; k++) s += f[k] * symW[j * 10 + k];
        hr[16 + j] = eluf(s);
    }
}

// one warp per row: bitmap -> canonical uint16 list in gmem, then RE-ZERO the
// bitmap row (restores the all-zero invariant for the next graph replay).
__global__ void k_build() {
    int warp = threadIdx.x >> 5;
    int lane = threadIdx.x & 31;
    int i = blockIdx.x * 8 + warp;

    unsigned* fw = g_bf + (i << 8);
    unsigned* rv = g_br + (i << 8);
    unsigned short* dst = g_nbr + i * LISTCAP;
    int total = 0;
    for (int it = 0; it < 8; it++) {
        int wi = it * 32 + lane;
        unsigned f = fw[wi];
        unsigned r = rv[wi];
        unsigned u = f | r;
        int cnt = __popc(u);
        int pre = cnt;
#pragma unroll
        for (int o = 1; o < 32; o <<= 1) {
            int t = __shfl_up_sync(0xffffffffu, pre, o);
            if (lane >= o) pre += t;
        }
        int wtot = __shfl_sync(0xffffffffu, pre, 31);
        int pos = total + pre - cnt;
        while (u) {
            int b = __ffs(u) - 1;
            u &= u - 1;
            unsigned F = (f >> b) & 1;
            unsigned R = (r >> b) & 1;
            if (pos < LISTCAP)
                dst[pos] = (unsigned short)((wi * 32 + b) | (F << 13) | (R << 14));
            pos++;
        }
        total += wtot;
        fw[wi] = 0u;           // restore zero invariant
        rv[wi] = 0u;
    }
    if (total > LISTCAP) total = LISTCAP;
    if (lane == 0) g_cnt[i] = total;
}

// Fused: ht = h[:, :K] @ W^T ; asrc/adst = ht @ att ; column partial sums.
__global__ void k_gemm_fused(const float* __restrict__ W,
                             const float* __restrict__ att, int K) {
    __shared__ __align__(16) float Ws[64][68];
    __shared__ float As[64][65];
    __shared__ float sAtt[128];
    __shared__ float spart[8][64];

    int tid = threadIdx.x;
    int rowBase = blockIdx.x * 64;

    if (blockIdx.x == 0 && tid == 0) g_fillbits = 0u;   // reset for this layer

    for (int idx = tid; idx < 64 * K; idx += 256) {
        int c = idx / K, k = idx % K;
        Ws[k][c] = W[idx];
    }
    for (int idx = tid; idx < 64 * K; idx += 256) {
        int r = idx / K, k = idx % K;
        As[r][k] = g_h[(rowBase + r) * 64 + k];
    }
    if (tid < 128) sAtt[tid] = att[tid];
    __syncthreads();

    int cg = tid & 7;
    int rg = tid >> 3;
    int r0 = rg * 2;
    int c0 = cg * 8;

    float acc0[8] = {}, acc1[8] = {};
    for (int k = 0; k < K; k++) {
        float a0 = As[r0][k];
        float a1 = As[r0 + 1][k];
        float4 w0 = *(const float4*)&Ws[k][c0];
        float4 w1 = *(const float4*)&Ws[k][c0 + 4];
        acc0[0] += a0 * w0.x; acc0[1] += a0 * w0.y; acc0[2] += a0 * w0.z; acc0[3] += a0 * w0.w;
        acc0[4] += a0 * w1.x; acc0[5] += a0 * w1.y; acc0[6] += a0 * w1.z; acc0[7] += a0 * w1.w;
        acc1[0] += a1 * w0.x; acc1[1] += a1 * w0.y; acc1[2] += a1 * w0.z; acc1[3] += a1 * w0.w;
        acc1[4] += a1 * w1.x; acc1[5] += a1 * w1.y; acc1[6] += a1 * w1.z; acc1[7] += a1 * w1.w;
    }

    int R0 = rowBase + r0;
    float4* hp0 = (float4*)(g_ht + R0 * 64 + c0);
    float4* hp1 = (float4*)(g_ht + (R0 + 1) * 64 + c0);
    hp0[0] = make_float4(acc0[0], acc0[1], acc0[2], acc0[3]);
    hp0[1] = make_float4(acc0[4], acc0[5], acc0[6], acc0[7]);
    hp1[0] = make_float4(acc1[0], acc1[1], acc1[2], acc1[3]);
    hp1[1] = make_float4(acc1[4], acc1[5], acc1[6], acc1[7]);

    float s0 = 0.f, d0 = 0.f, s1 = 0.f, d1 = 0.f;
#pragma unroll
    for (int m = 0; m < 8; m++) {
        float aw = sAtt[c0 + m], dw = sAtt[64 + c0 + m];
        s0 += acc0[m] * aw;  d0 += acc0[m] * dw;
        s1 += acc1[m] * aw;  d1 += acc1[m] * dw;
    }
#pragma unroll
    for (int o = 1; o < 8; o <<= 1) {
        s0 += __shfl_xor_sync(0xffffffffu, s0, o);
        d0 += __shfl_xor_sync(0xffffffffu, d0, o);
        s1 += __shfl_xor_sync(0xffffffffu, s1, o);
        d1 += __shfl_xor_sync(0xffffffffu, d1, o);
    }
    if (cg == 0) {
        g_asrc[R0] = s0;  g_adst[R0] = d0;
        g_asrc[R0 + 1] = s1;  g_adst[R0 + 1] = d1;
    }

    int lane = tid & 31, warp = tid >> 5;
    float colv[8];
#pragma unroll
    for (int m = 0; m < 8; m++) {
        float v = acc0[m] + acc1[m];
        v += __shfl_xor_sync(0xffffffffu, v, 8);
        v += __shfl_xor_sync(0xffffffffu, v, 16);
        colv[m] = v;
    }
    if (lane < 8) {
#pragma unroll
        for (int m = 0; m < 8; m++) spart[warp][lane * 8 + m] = colv[m];
    }
    __syncthreads();
    if (tid < 64) {
        float s = 0.f;
#pragma unroll
        for (int w = 0; w < 8; w++) s += spart[w][tid];
        g_part[blockIdx.x * 64 + tid] = s;
    }
}

// edge-max (fill) with smem-staged asrc/adst + Ssum reduction (block 0).
// grid MUST be EM_BLOCKS(128) x 256: each block owns 2048 edges, 8 per thread.
__global__ void k_edge_max(const int* __restrict__ ei) {
    __shared__ __align__(16) float stage[N];   // 32 KB; asrc then adst
    __shared__ float red[256];
    __shared__ float wred[8];
    int tid = threadIdx.x;

    if (blockIdx.x == 0) {       // Ssum final reduction
        int col = tid & 63, q = tid >> 6;
        float s = 0.f;
        for (int b = q; b < GEMM_BLOCKS; b += 4) s += g_part[b * 64 + col];
        red[tid] = s;
        __syncthreads();
        if (tid < 64) g_Ssum[tid] = red[tid] + red[64 + tid] + red[128 + tid] + red[192 + tid];
    }

    // stage asrc
    for (int t = tid; t < N / 4; t += 256)
        ((float4*)stage)[t] = ((const float4*)g_asrc)[t];
    __syncthreads();

    int k0 = blockIdx.x * 2048 + tid * 8;
    int4 ra = *(const int4*)(ei + k0);
    int4 rb = *(const int4*)(ei + k0 + 4);
    float NEG = -3.0e38f;
    float p[8];
    p[0] = ((unsigned)ra.x < N) ? stage[ra.x & 8191] : NEG;
    p[1] = ((unsigned)ra.y < N) ? stage[ra.y & 8191] : NEG;
    p[2] = ((unsigned)ra.z < N) ? stage[ra.z & 8191] : NEG;
    p[3] = ((unsigned)ra.w < N) ? stage[ra.w & 8191] : NEG;
    p[4] = ((unsigned)rb.x < N) ? stage[rb.x & 8191] : NEG;
    p[5] = ((unsigned)rb.y < N) ? stage[rb.y & 8191] : NEG;
    p[6] = ((unsigned)rb.z < N) ? stage[rb.z & 8191] : NEG;
    p[7] = ((unsigned)rb.w < N) ? stage[rb.w & 8191] : NEG;
    __syncthreads();

    // restage adst
    for (int t = tid; t < N / 4; t += 256)
        ((float4*)stage)[t] = ((const float4*)g_adst)[t];
    __syncthreads();

    int4 ca = *(const int4*)(ei + E + k0);
    int4 cb = *(const int4*)(ei + E + k0 + 4);
    float q0 = ((unsigned)ca.x < N) ? stage[ca.x & 8191] : NEG;
    float q1 = ((unsigned)ca.y < N) ? stage[ca.y & 8191] : NEG;
    float q2 = ((unsigned)ca.z < N) ? stage[ca.z & 8191] : NEG;
    float q3 = ((unsigned)ca.w < N) ? stage[ca.w & 8191] : NEG;
    float q4 = ((unsigned)cb.x < N) ? stage[cb.x & 8191] : NEG;
    float q5 = ((unsigned)cb.y < N) ? stage[cb.y & 8191] : NEG;
    float q6 = ((unsigned)cb.z < N) ? stage[cb.z & 8191] : NEG;
    float q7 = ((unsigned)cb.w < N) ? stage[cb.w & 8191] : NEG;

    float m = fmaxf(fmaxf(fmaxf(p[0] + q0, p[1] + q1), fmaxf(p[2] + q2, p[3] + q3)),
                    fmaxf(fmaxf(p[4] + q4, p[5] + q5), fmaxf(p[6] + q6, p[7] + q7)));
#pragma unroll
    for (int o = 16; o; o >>= 1) m = fmaxf(m, __shfl_xor_sync(0xffffffffu, m, o));
    int warp = tid >> 5;
    if ((tid & 31) == 0) wred[warp] = m;
    __syncthreads();
    if (tid == 0) {
        float bm = wred[0];
#pragma unroll
        for (int w = 1; w < 8; w++) bm = fmaxf(bm, wred[w]);
        atomicMax(&g_fillbits, fmap(lrelu(bm)));   // lrelu monotone
    }
}

// one warp per row: sparse softmax-aggregate; neighbor list precomputed in gmem
__global__ void k_agg(int residual) {
    __shared__ unsigned short list[8][LISTCAP];
    __shared__ float wbuf[8][LISTCAP];
    int warp = threadIdx.x >> 5;
    int lane = threadIdx.x & 31;
    int i = blockIdx.x * 8 + warp;

    int total = g_cnt[i];
    const unsigned* src = (const unsigned*)(g_nbr + i * LISTCAP);
    unsigned* dstw = (unsigned*)&list[warp][0];
    for (int t = lane; t * 2 < total; t += 32) dstw[t] = src[t];
    __syncwarp();

    // phase A: parallel weight computation
    float fill = funmap(g_fillbits);
    float enf = expf(-fill);
    float ai = g_asrc[i];
    float di = g_adst[i];
    float z = 0.f;
    for (int n = lane; n < total; n += 32) {
        unsigned ent = list[warp][n];
        int j = ent & 8191;
        float aj = g_asrc[j];
        float dj = g_adst[j];
        float e1 = (ent & (1u << 13)) ? lrelu(ai + dj) : 0.f;
        float e2 = (ent & (1u << 14)) ? lrelu(aj + di) : 0.f;
        float w = expf(0.5f * (e1 + e2) - fill) - enf;
        wbuf[warp][n] = w;
        z += w;
    }
#pragma unroll
    for (int o = 16; o; o >>= 1) z += __shfl_xor_sync(0xffffffffu, z, o);
    __syncwarp();

    // phase B: serial weighted accumulation, unroll 4
    int c0 = lane * 2;
    float acc0 = 0.f, acc1 = 0.f;
    int n = 0;
    for (; n + 3 < total; n += 4) {
        float w0 = wbuf[warp][n],     w1 = wbuf[warp][n + 1];
        float w2 = wbuf[warp][n + 2], w3 = wbuf[warp][n + 3];
        int j0 = list[warp][n] & 8191,     j1 = list[warp][n + 1] & 8191;
        int j2 = list[warp][n + 2] & 8191, j3 = list[warp][n + 3] & 8191;
        float2 h0 = *(const float2*)(g_ht + j0 * 64 + c0);
        float2 h1 = *(const float2*)(g_ht + j1 * 64 + c0);
        float2 h2 = *(const float2*)(g_ht + j2 * 64 + c0);
        float2 h3 = *(const float2*)(g_ht + j3 * 64 + c0);
        acc0 += w0 * h0.x + w1 * h1.x + w2 * h2.x + w3 * h3.x;
        acc1 += w0 * h0.y + w1 * h1.y + w2 * h2.y + w3 * h3.y;
    }
    for (; n < total; n++) {
        float w0 = wbuf[warp][n];
        int j0 = list[warp][n] & 8191;
        float2 h0 = *(const float2*)(g_ht + j0 * 64 + c0);
        acc0 += w0 * h0.x;
        acc1 += w0 * h0.y;
    }

    float Z = 1.f + 8191.f * enf + z;
    float hi0 = g_ht[i * 64 + c0];
    float hi1 = g_ht[i * 64 + c0 + 1];
    float r0 = (acc0 + enf * g_Ssum[c0]     + (1.f - enf) * hi0) / Z;
    float r1 = (acc1 + enf * g_Ssum[c0 + 1] + (1.f - enf) * hi1) / Z;
    float o0 = eluf(r0);
    float o1 = eluf(r1);
    if (residual) {
        g_h[i * 64 + c0]     += o0;
        g_h[i * 64 + c0 + 1] += o1;
    } else {
        g_h[i * 64 + c0]     = o0;
        g_h[i * 64 + c0 + 1] = o1;
    }
}

__global__ void k_heads(const float* __restrict__ rW1, const float* __restrict__ rb1,
                        const float* __restrict__ rW2, const float* __restrict__ rb2,
                        const float* __restrict__ cW1, const float* __restrict__ cb1,
                        const float* __restrict__ cW2, const float* __restrict__ cb2,
                        float* __restrict__ out) {
    __shared__ float sRW1[32][65];
    __shared__ float sCW1[32][65];
    __shared__ float sRW2[32];
    __shared__ float sCW2[128];
    __shared__ float sRb1[32];
    __shared__ float sCb1[32];
    int tid = threadIdx.x;
    for (int idx = tid; idx < 2048; idx += 256) {
        sRW1[idx >> 6][idx & 63] = rW1[idx];
        sCW1[idx >> 6][idx & 63] = cW1[idx];
    }
    if (tid < 32) { sRW2[tid] = rW2[tid]; sRb1[tid] = rb1[tid]; sCb1[tid] = cb1[tid]; }
    if (tid < 128) sCW2[tid] = cW2[tid];
    __syncthreads();

    int warp = tid >> 5;
    int lane = tid & 31;
    int i = blockIdx.x * 8 + warp;
    const float* h = g_h + i * 64;

    float t1 = sRb1[lane];
    float t2 = sCb1[lane];
    for (int k = 0; k < 64; k++) {
        float hv = h[k];
        t1 += hv * sRW1[lane][k];
        t2 += hv * sCW1[lane][k];
    }
    t1 = eluf(t1);
    t2 = eluf(t2);

    float p = t1 * sRW2[lane];
#pragma unroll
    for (int o = 16; o; o >>= 1) p += __shfl_xor_sync(0xffffffffu, p, o);
    if (lane == 0) out[i] = p + rb2[0];

#pragma unroll
    for (int k = 0; k < 4; k++) {
        float q = t2 * sCW2[k * 32 + lane];
#pragma unroll
        for (int o = 16; o; o >>= 1) q += __shfl_xor_sync(0xffffffffu, q, o);
        if (lane == 0) out[N + i * 4 + k] = q + cb2[k];
    }

    float2 hv = *(const float2*)(h + lane * 2);
    ((float2*)(out + N + 4 * N))[i * 32 + lane] = hv;
}

// ---------------- launch ----------------
extern "C" void kernel_launch(void* const* d_in, const int* in_sizes, int n_in,
                              void* d_out, int out_size) {
    const float* x    = (const float*)d_in[0];
    const int*   ei   = (const int*)d_in[1];   // int32 (JAX downcast)
    const float* symW = (const float*)d_in[3];
    const float* symb = (const float*)d_in[4];
    const float* W0   = (const float*)d_in[5];
    const float* att0 = (const float*)d_in[6];
    const float* W1   = (const float*)d_in[7];
    const float* att1 = (const float*)d_in[8];
    const float* W2   = (const float*)d_in[9];
    const float* att2 = (const float*)d_in[10];
    const float* rW1  = (const float*)d_in[11];
    const float* rb1  = (const float*)d_in[12];
    const float* rW2  = (const float*)d_in[13];
    const float* rb2  = (const float*)d_in[14];
    const float* cW1  = (const float*)d_in[15];
    const float* cb1  = (const float*)d_in[16];
    const float* cW2  = (const float*)d_in[17];
    const float* cb2  = (const float*)d_in[18];
    float* out = (float*)d_out;

    k_setbits_feat<<<SB_BLOCKS, 256>>>(ei, x, symW, symb);
    k_build<<<1024, 256>>>();

    const float* Ws[3]   = { W0, W1, W2 };
    const float* atts[3] = { att0, att1, att2 };
    int Kd[3] = { 48, 64, 64 };
    for (int L = 0; L < 3; L++) {
        k_gemm_fused<<<GEMM_BLOCKS, 256>>>(Ws[L], atts[L], Kd[L]);
        k_edge_max<<<EM_BLOCKS, 256>>>(ei);
        k_agg<<<1024, 256>>>(L > 0 ? 1 : 0);
    }
    k_heads<<<1024, 256>>>(rW1, rb1, rW2, rb2, cW1, cb1, cW2, cb2, out);
}

// round 11
// speedup vs baseline: 1.0656x; 1.0656x over previous
#include <cuda_runtime.h>
#include <cstdint>
#include <math.h>

#define N 8192
#define E 262144
#define NW 256              // bitmap words per row (8192 bits / 32)
#define LISTCAP 256         // max union degree; Poisson(~64) tail @256 ~ 0
#define GEMM_BLOCKS 128     // 64 rows per block
#define SB_BLOCKS 512       // setbits: 2 edges per thread
#define EM_BLOCKS 512       // edge_max: 2 edges per thread (R8 shape — measured best)

// ---------------- scratch (device globals; zero-initialized at module load) --
__device__ __align__(16) float          g_h[N * 64];
__device__ __align__(16) float          g_ht[N * 64];
__device__ __align__(16) float          g_asrc[N];
__device__ __align__(16) float          g_adst[N];
__device__ __align__(16) float          g_Ssum[64];
__device__ __align__(16) float          g_part[GEMM_BLOCKS * 64];
__device__ unsigned                     g_fillbits;
__device__ __align__(16) unsigned       g_bf[N * NW];     // cleared by k_build after use
__device__ __align__(16) unsigned       g_br[N * NW];     // cleared by k_build after use
__device__ __align__(16) unsigned short g_nbr[N * LISTCAP];  // per-row union list
__device__ __align__(16) int            g_cnt[N];

// ---------------- helpers ----------------
__device__ __forceinline__ float eluf(float x)  { return x > 0.f ? x : expf(x) - 1.f; }
__device__ __forceinline__ float lrelu(float x) { return x > 0.f ? x : 0.2f * x; }
__device__ __forceinline__ unsigned fmap(float f) {
    unsigned u = __float_as_uint(f);
    return (u & 0x80000000u) ? ~u : (u | 0x80000000u);
}
__device__ __forceinline__ float funmap(unsigned u) {
    return (u & 0x80000000u) ? __uint_as_float(u & 0x7fffffffu) : __uint_as_float(~u);
}

// ---------------- kernels ----------------
// set adjacency bits; threads with gid < N also compute symbolic features.
// edge_index is int32 (JAX downcasts int64 without x64 mode).
__global__ void k_setbits_feat(const int* __restrict__ ei,
                               const float* __restrict__ x,
                               const float* __restrict__ symW,
                               const float* __restrict__ symb) {
    int gid = blockIdx.x * blockDim.x + threadIdx.x;
    int k0 = gid * 2;
    if (k0 < E) {
        int2 r2 = *(const int2*)(ei + k0);
        int2 c2 = *(const int2*)(ei + E + k0);
        if ((unsigned)r2.x < N && (unsigned)c2.x < N && r2.x != c2.x) {
            atomicOr(&g_bf[(r2.x << 8) + (c2.x >> 5)], 1u << (c2.x & 31));
            atomicOr(&g_br[(c2.x << 8) + (r2.x >> 5)], 1u << (r2.x & 31));
        }
        if ((unsigned)r2.y < N && (unsigned)c2.y < N && r2.y != c2.y) {
            atomicOr(&g_bf[(r2.y << 8) + (c2.y >> 5)], 1u << (c2.y & 31));
            atomicOr(&g_br[(c2.y << 8) + (r2.y >> 5)], 1u << (r2.y & 31));
        }
    }

    int i = gid;
    if (i >= N) return;
    const float* xr = x + i * 16;
    float am = xr[0], bod = xr[1], dox = xr[2], ph = xr[4], ni = xr[7];

    float p_ph  = ph  < 6.5f   ? (6.5f - ph) / 6.5f     : (ph  > 8.5f ? (ph  - 8.5f) / 8.5f : 0.f);
    float p_am  = am  < 0.001f ? (0.001f - am) / 0.001f : (am  > 0.5f ? (am  - 0.5f) / 0.5f : 0.f);
    float p_bod = bod < 0.001f ? (0.001f - bod) / 0.001f: (bod > 5.0f ? (bod - 5.0f) / 5.0f : 0.f);
    float p_do  = dox < 6.0f   ? (6.0f - dox) / 6.0f    : 0.f;
    float p_ni  = ni  < 0.001f ? (0.001f - ni) / 0.001f : (ni  > 10.f ? (ni  - 10.f) / 10.f : 0.f);

    float bact = (1.2f * am / 0.5f + 1.5f * bod / 5.0f - 0.8f * dox / 10.0f) * (1.f / 3.f);
    float chem = (1.5f * ph / 8.5f + ni / 10.0f) * 0.5f;
    float org  = (2.0f * bod / 5.0f - 1.5f * dox / 10.0f + 0.8f * am / 0.5f) * (1.f / 3.f);
    float agri = 2.0f * ni / 10.0f;
    float comp = 1.f / (1.f + (p_ph + p_am + p_bod + p_do + p_ni) + 1e-8f);

    float f[10] = { p_ph, p_am, p_bod, p_do, p_ni, bact, chem, org, agri, comp };
    float* hr = g_h + i * 64;
#pragma unroll
    for (int k = 0; k < 16; k++) hr[k] = xr[k];
    for (int j = 0; j < 32; j++) {
        float s = symb[j];
#pragma unroll
        for (int k = 0; k < 10; k++) s += f[k] * symW[j * 10 + k];
        hr[16 + j] = eluf(s);
    }
}

// one warp per row: bitmap -> canonical uint16 list in gmem, then RE-ZERO the
// bitmap row (restores the all-zero invariant for the next graph replay).
__global__ void k_build() {
    int warp = threadIdx.x >> 5;
    int lane = threadIdx.x & 31;
    int i = blockIdx.x * 8 + warp;

    unsigned* fw = g_bf + (i << 8);
    unsigned* rv = g_br + (i << 8);
    unsigned short* dst = g_nbr + i * LISTCAP;
    int total = 0;
    for (int it = 0; it < 8; it++) {
        int wi = it * 32 + lane;
        unsigned f = fw[wi];
        unsigned r = rv[wi];
        unsigned u = f | r;
        int cnt = __popc(u);
        int pre = cnt;
#pragma unroll
        for (int o = 1; o < 32; o <<= 1) {
            int t = __shfl_up_sync(0xffffffffu, pre, o);
            if (lane >= o) pre += t;
        }
        int wtot = __shfl_sync(0xffffffffu, pre, 31);
        int pos = total + pre - cnt;
        while (u) {
            int b = __ffs(u) - 1;
            u &= u - 1;
            unsigned F = (f >> b) & 1;
            unsigned R = (r >> b) & 1;
            if (pos < LISTCAP)
                dst[pos] = (unsigned short)((wi * 32 + b) | (F << 13) | (R << 14));
            pos++;
        }
        total += wtot;
        fw[wi] = 0u;           // restore zero invariant
        rv[wi] = 0u;
    }
    if (total > LISTCAP) total = LISTCAP;
    if (lane == 0) g_cnt[i] = total;
}

// Fused: ht = h[:, :K] @ W^T ; asrc/adst = ht @ att ; column partial sums.
__global__ void k_gemm_fused(const float* __restrict__ W,
                             const float* __restrict__ att, int K) {
    __shared__ __align__(16) float Ws[64][68];
    __shared__ float As[64][65];
    __shared__ float sAtt[128];
    __shared__ float spart[8][64];

    int tid = threadIdx.x;
    int rowBase = blockIdx.x * 64;

    if (blockIdx.x == 0 && tid == 0) g_fillbits = 0u;   // reset for this layer

    for (int idx = tid; idx < 64 * K; idx += 256) {
        int c = idx / K, k = idx % K;
        Ws[k][c] = W[idx];
    }
    for (int idx = tid; idx < 64 * K; idx += 256) {
        int r = idx / K, k = idx % K;
        As[r][k] = g_h[(rowBase + r) * 64 + k];
    }
    if (tid < 128) sAtt[tid] = att[tid];
    __syncthreads();

    int cg = tid & 7;
    int rg = tid >> 3;
    int r0 = rg * 2;
    int c0 = cg * 8;

    float acc0[8] = {}, acc1[8] = {};
    for (int k = 0; k < K; k++) {
        float a0 = As[r0][k];
        float a1 = As[r0 + 1][k];
        float4 w0 = *(const float4*)&Ws[k][c0];
        float4 w1 = *(const float4*)&Ws[k][c0 + 4];
        acc0[0] += a0 * w0.x; acc0[1] += a0 * w0.y; acc0[2] += a0 * w0.z; acc0[3] += a0 * w0.w;
        acc0[4] += a0 * w1.x; acc0[5] += a0 * w1.y; acc0[6] += a0 * w1.z; acc0[7] += a0 * w1.w;
        acc1[0] += a1 * w0.x; acc1[1] += a1 * w0.y; acc1[2] += a1 * w0.z; acc1[3] += a1 * w0.w;
        acc1[4] += a1 * w1.x; acc1[5] += a1 * w1.y; acc1[6] += a1 * w1.z; acc1[7] += a1 * w1.w;
    }

    int R0 = rowBase + r0;
    float4* hp0 = (float4*)(g_ht + R0 * 64 + c0);
    float4* hp1 = (float4*)(g_ht + (R0 + 1) * 64 + c0);
    hp0[0] = make_float4(acc0[0], acc0[1], acc0[2], acc0[3]);
    hp0[1] = make_float4(acc0[4], acc0[5], acc0[6], acc0[7]);
    hp1[0] = make_float4(acc1[0], acc1[1], acc1[2], acc1[3]);
    hp1[1] = make_float4(acc1[4], acc1[5], acc1[6], acc1[7]);

    float s0 = 0.f, d0 = 0.f, s1 = 0.f, d1 = 0.f;
#pragma unroll
    for (int m = 0; m < 8; m++) {
        float aw = sAtt[c0 + m], dw = sAtt[64 + c0 + m];
        s0 += acc0[m] * aw;  d0 += acc0[m] * dw;
        s1 += acc1[m] * aw;  d1 += acc1[m] * dw;
    }
#pragma unroll
    for (int o = 1; o < 8; o <<= 1) {
        s0 += __shfl_xor_sync(0xffffffffu, s0, o);
        d0 += __shfl_xor_sync(0xffffffffu, d0, o);
        s1 += __shfl_xor_sync(0xffffffffu, s1, o);
        d1 += __shfl_xor_sync(0xffffffffu, d1, o);
    }
    if (cg == 0) {
        g_asrc[R0] = s0;  g_adst[R0] = d0;
        g_asrc[R0 + 1] = s1;  g_adst[R0 + 1] = d1;
    }

    int lane = tid & 31, warp = tid >> 5;
    float colv[8];
#pragma unroll
    for (int m = 0; m < 8; m++) {
        float v = acc0[m] + acc1[m];
        v += __shfl_xor_sync(0xffffffffu, v, 8);
        v += __shfl_xor_sync(0xffffffffu, v, 16);
        colv[m] = v;
    }
    if (lane < 8) {
#pragma unroll
        for (int m = 0; m < 8; m++) spart[warp][lane * 8 + m] = colv[m];
    }
    __syncthreads();
    if (tid < 64) {
        float s = 0.f;
#pragma unroll
        for (int w = 0; w < 8; w++) s += spart[w][tid];
        g_part[blockIdx.x * 64 + tid] = s;
    }
}

// edge-max (fill) + Ssum reduction (block 0). grid = EM_BLOCKS(512) x 256,
// 2 edges per thread — measured best shape (R8).
__global__ void k_edge_max(const int* __restrict__ ei) {
    __shared__ float wmax[8];
    if (blockIdx.x == 0) {
        __shared__ float red[256];
        int t = threadIdx.x;
        int col = t & 63, q = t >> 6;
        float s = 0.f;
        for (int b = q; b < GEMM_BLOCKS; b += 4) s += g_part[b * 64 + col];
        red[t] = s;
        __syncthreads();
        if (t < 64) g_Ssum[t] = red[t] + red[64 + t] + red[128 + t] + red[192 + t];
    }
    int k0 = (blockIdx.x * 256 + threadIdx.x) * 2;   // covers E exactly
    int2 r2 = *(const int2*)(ei + k0);
    int2 c2 = *(const int2*)(ei + E + k0);
    float NEG = -3.0e38f;
    float a0 = ((unsigned)r2.x < N) ? g_asrc[r2.x] : NEG;
    float a1 = ((unsigned)r2.y < N) ? g_asrc[r2.y] : NEG;
    float b0 = ((unsigned)c2.x < N) ? g_adst[c2.x] : NEG;
    float b1 = ((unsigned)c2.y < N) ? g_adst[c2.y] : NEG;
    float m = fmaxf(a0 + b0, a1 + b1);
#pragma unroll
    for (int o = 16; o; o >>= 1) m = fmaxf(m, __shfl_xor_sync(0xffffffffu, m, o));
    int warp = threadIdx.x >> 5;
    if ((threadIdx.x & 31) == 0) wmax[warp] = m;
    __syncthreads();
    if (threadIdx.x == 0) {
        float bm = wmax[0];
#pragma unroll
        for (int w = 1; w < 8; w++) bm = fmaxf(bm, wmax[w]);
        atomicMax(&g_fillbits, fmap(lrelu(bm)));    // lrelu monotone
    }
}

// Shared aggregation core: computes the post-ELU aggregate for row i.
// Returns via o0/o1 (the two columns owned by this lane).
__device__ __forceinline__ void agg_core(int i, int warp, int lane,
                                         unsigned short (*list)[LISTCAP],
                                         float (*wbuf)[LISTCAP],
                                         float& o0, float& o1) {
    int total = g_cnt[i];
    const unsigned* src = (const unsigned*)(g_nbr + i * LISTCAP);
    unsigned* dstw = (unsigned*)&list[warp][0];
    for (int t = lane; t * 2 < total; t += 32) dstw[t] = src[t];
    __syncwarp();

    float fill = funmap(g_fillbits);
    float enf = expf(-fill);
    float ai = g_asrc[i];
    float di = g_adst[i];
    float z = 0.f;
    for (int n = lane; n < total; n += 32) {
        unsigned ent = list[warp][n];
        int j = ent & 8191;
        float aj = g_asrc[j];
        float dj = g_adst[j];
        float e1 = (ent & (1u << 13)) ? lrelu(ai + dj) : 0.f;
        float e2 = (ent & (1u << 14)) ? lrelu(aj + di) : 0.f;
        float w = expf(0.5f * (e1 + e2) - fill) - enf;
        wbuf[warp][n] = w;
        z += w;
    }
#pragma unroll
    for (int o = 16; o; o >>= 1) z += __shfl_xor_sync(0xffffffffu, z, o);
    __syncwarp();

    int c0 = lane * 2;
    float acc0 = 0.f, acc1 = 0.f;
    int n = 0;
    for (; n + 3 < total; n += 4) {
        float w0 = wbuf[warp][n],     w1 = wbuf[warp][n + 1];
        float w2 = wbuf[warp][n + 2], w3 = wbuf[warp][n + 3];
        int j0 = list[warp][n] & 8191,     j1 = list[warp][n + 1] & 8191;
        int j2 = list[warp][n + 2] & 8191, j3 = list[warp][n + 3] & 8191;
        float2 h0 = *(const float2*)(g_ht + j0 * 64 + c0);
        float2 h1 = *(const float2*)(g_ht + j1 * 64 + c0);
        float2 h2 = *(const float2*)(g_ht + j2 * 64 + c0);
        float2 h3 = *(const float2*)(g_ht + j3 * 64 + c0);
        acc0 += w0 * h0.x + w1 * h1.x + w2 * h2.x + w3 * h3.x;
        acc1 += w0 * h0.y + w1 * h1.y + w2 * h2.y + w3 * h3.y;
    }
    for (; n < total; n++) {
        float w0 = wbuf[warp][n];
        int j0 = list[warp][n] & 8191;
        float2 h0 = *(const float2*)(g_ht + j0 * 64 + c0);
        acc0 += w0 * h0.x;
        acc1 += w0 * h0.y;
    }

    float Z = 1.f + 8191.f * enf + z;
    float hi0 = g_ht[i * 64 + c0];
    float hi1 = g_ht[i * 64 + c0 + 1];
    float r0 = (acc0 + enf * g_Ssum[c0]     + (1.f - enf) * hi0) / Z;
    float r1 = (acc1 + enf * g_Ssum[c0 + 1] + (1.f - enf) * hi1) / Z;
    o0 = eluf(r0);
    o1 = eluf(r1);
}

// layers 0/1: lean smem (12 KB)
__global__ void k_agg(int residual) {
    __shared__ unsigned short list[8][LISTCAP];
    __shared__ float wbuf[8][LISTCAP];
    int warp = threadIdx.x >> 5;
    int lane = threadIdx.x & 31;
    int i = blockIdx.x * 8 + warp;
    int c0 = lane * 2;

    float o0, o1;
    agg_core(i, warp, lane, list, wbuf, o0, o1);

    if (residual) {
        g_h[i * 64 + c0]     += o0;
        g_h[i * 64 + c0 + 1] += o1;
    } else {
        g_h[i * 64 + c0]     = o0;
        g_h[i * 64 + c0 + 1] = o1;
    }
}

// layer 2: aggregation + residual + both head MLPs + output writes (separate
// kernel so layers 0/1 keep lean smem / high occupancy)
__global__ void k_agg_heads(const float* __restrict__ rW1, const float* __restrict__ rb1,
                            const float* __restrict__ rW2, const float* __restrict__ rb2,
                            const float* __restrict__ cW1, const float* __restrict__ cb1,
                            const float* __restrict__ cW2, const float* __restrict__ cb2,
                            float* __restrict__ out) {
    __shared__ unsigned short list[8][LISTCAP];
    __shared__ float wbuf[8][LISTCAP];
    __shared__ float sRW1[32][65];
    __shared__ float sCW1[32][65];
    __shared__ float sRW2[32];
    __shared__ float sCW2[128];
    __shared__ float sRb1[32];
    __shared__ float sCb1[32];
    __shared__ float srow[8][64];

    int tid = threadIdx.x;
    int warp = tid >> 5;
    int lane = tid & 31;
    int i = blockIdx.x * 8 + warp;
    int c0 = lane * 2;

    for (int idx = tid; idx < 2048; idx += 256) {
        sRW1[idx >> 6][idx & 63] = rW1[idx];
        sCW1[idx >> 6][idx & 63] = cW1[idx];
    }
    if (tid < 32) { sRW2[tid] = rW2[tid]; sRb1[tid] = rb1[tid]; sCb1[tid] = cb1[tid]; }
    if (tid < 128) sCW2[tid] = cW2[tid];
    __syncthreads();

    float o0, o1;
    agg_core(i, warp, lane, list, wbuf, o0, o1);

    float h0 = g_h[i * 64 + c0]     + o0;
    float h1 = g_h[i * 64 + c0 + 1] + o1;
    srow[warp][c0]     = h0;
    srow[warp][c0 + 1] = h1;
    __syncwarp();

    float t1 = sRb1[lane];
    float t2 = sCb1[lane];
#pragma unroll
    for (int k = 0; k < 64; k++) {
        float hv = srow[warp][k];
        t1 += hv * sRW1[lane][k];
        t2 += hv * sCW1[lane][k];
    }
    t1 = eluf(t1);
    t2 = eluf(t2);

    float p = t1 * sRW2[lane];
#pragma unroll
    for (int o = 16; o; o >>= 1) p += __shfl_xor_sync(0xffffffffu, p, o);
    if (lane == 0) out[i] = p + rb2[0];

#pragma unroll
    for (int k = 0; k < 4; k++) {
        float q = t2 * sCW2[k * 32 + lane];
#pragma unroll
        for (int o = 16; o; o >>= 1) q += __shfl_xor_sync(0xffffffffu, q, o);
        if (lane == 0) out[N + i * 4 + k] = q + cb2[k];
    }

    ((float2*)(out + N + 4 * N))[i * 32 + lane] = make_float2(h0, h1);
}

// ---------------- launch ----------------
extern "C" void kernel_launch(void* const* d_in, const int* in_sizes, int n_in,
                              void* d_out, int out_size) {
    const float* x    = (const float*)d_in[0];
    const int*   ei   = (const int*)d_in[1];   // int32 (JAX downcast)
    const float* symW = (const float*)d_in[3];
    const float* symb = (const float*)d_in[4];
    const float* W0   = (const float*)d_in[5];
    const float* att0 = (const float*)d_in[6];
    const float* W1   = (const float*)d_in[7];
    const float* att1 = (const float*)d_in[8];
    const float* W2   = (const float*)d_in[9];
    const float* att2 = (const float*)d_in[10];
    const float* rW1  = (const float*)d_in[11];
    const float* rb1  = (const float*)d_in[12];
    const float* rW2  = (const float*)d_in[13];
    const float* rb2  = (const float*)d_in[14];
    const float* cW1  = (const float*)d_in[15];
    const float* cb1  = (const float*)d_in[16];
    const float* cW2  = (const float*)d_in[17];
    const float* cb2  = (const float*)d_in[18];
    float* out = (float*)d_out;

    k_setbits_feat<<<SB_BLOCKS, 256>>>(ei, x, symW, symb);
    k_build<<<1024, 256>>>();

    const float* Ws[3]   = { W0, W1, W2 };
    const float* atts[3] = { att0, att1, att2 };
    int Kd[3] = { 48, 64, 64 };
    for (int L = 0; L < 3; L++) {
        k_gemm_fused<<<GEMM_BLOCKS, 256>>>(Ws[L], atts[L], Kd[L]);
        k_edge_max<<<EM_BLOCKS, 256>>>(ei);
        if (L < 2) {
            k_agg<<<1024, 256>>>(L);
        } else {
            k_agg_heads<<<1024, 256>>>(rW1, rb1, rW2, rb2, cW1, cb1, cW2, cb2, out);
        }
    }
}

// round 12
// speedup vs baseline: 1.0694x; 1.0036x over previous
#include <cuda_runtime.h>
#include <cuda_fp16.h>
#include <cstdint>
#include <math.h>

#define N 8192
#define E 262144
#define NW 256              // bitmap words per row (8192 bits / 32)
#define LISTCAP 256         // max union degree; Poisson(~64) tail @256 ~ 0
#define GEMM_BLOCKS 128     // 64 rows per block
#define SB_BLOCKS 512       // setbits: 2 edges per thread
#define EM_BLOCKS 512       // edge_max: 2 edges per thread (measured best)

// ---------------- scratch (device globals; zero-initialized at module load) --
__device__ __align__(16) float          g_h[N * 64];
__device__ __align__(16) float          g_ht[N * 64];
__device__ __align__(16) __half         g_hth[N * 64];   // fp16 shadow of ht (gathers only)
__device__ __align__(16) float          g_asrc[N];
__device__ __align__(16) float          g_adst[N];
__device__ __align__(16) float          g_Ssum[64];
__device__ __align__(16) float          g_part[GEMM_BLOCKS * 64];
__device__ unsigned                     g_fillbits;
__device__ __align__(16) unsigned       g_bf[N * NW];    // cleared by k_build after use
__device__ __align__(16) unsigned       g_br[N * NW];    // cleared by k_build after use
__device__ __align__(16) unsigned short g_nbr[N * LISTCAP];
__device__ __align__(16) int            g_cnt[N];

// ---------------- helpers ----------------
__device__ __forceinline__ float eluf(float x)  { return x > 0.f ? x : expf(x) - 1.f; }
__device__ __forceinline__ float lrelu(float x) { return x > 0.f ? x : 0.2f * x; }
__device__ __forceinline__ unsigned fmap(float f) {
    unsigned u = __float_as_uint(f);
    return (u & 0x80000000u) ? ~u : (u | 0x80000000u);
}
__device__ __forceinline__ float funmap(unsigned u) {
    return (u & 0x80000000u) ? __uint_as_float(u & 0x7fffffffu) : __uint_as_float(~u);
}
__device__ __forceinline__ unsigned h2u(__half2 h) {
    union { __half2 h; unsigned u; } c; c.h = h; return c.u;
}

// ---------------- kernels ----------------
// set adjacency bits; threads with gid < N also compute symbolic features.
// edge_index is int32 (JAX downcasts int64 without x64 mode).
__global__ void k_setbits_feat(const int* __restrict__ ei,
                               const float* __restrict__ x,
                               const float* __restrict__ symW,
                               const float* __restrict__ symb) {
    int gid = blockIdx.x * blockDim.x + threadIdx.x;
    int k0 = gid * 2;
    if (k0 < E) {
        int2 r2 = *(const int2*)(ei + k0);
        int2 c2 = *(const int2*)(ei + E + k0);
        if ((unsigned)r2.x < N && (unsigned)c2.x < N && r2.x != c2.x) {
            atomicOr(&g_bf[(r2.x << 8) + (c2.x >> 5)], 1u << (c2.x & 31));
            atomicOr(&g_br[(c2.x << 8) + (r2.x >> 5)], 1u << (r2.x & 31));
        }
        if ((unsigned)r2.y < N && (unsigned)c2.y < N && r2.y != c2.y) {
            atomicOr(&g_bf[(r2.y << 8) + (c2.y >> 5)], 1u << (c2.y & 31));
            atomicOr(&g_br[(c2.y << 8) + (r2.y >> 5)], 1u << (r2.y & 31));
        }
    }

    int i = gid;
    if (i >= N) return;
    const float* xr = x + i * 16;
    float am = xr[0], bod = xr[1], dox = xr[2], ph = xr[4], ni = xr[7];

    float p_ph  = ph  < 6.5f   ? (6.5f - ph) / 6.5f     : (ph  > 8.5f ? (ph  - 8.5f) / 8.5f : 0.f);
    float p_am  = am  < 0.001f ? (0.001f - am) / 0.001f : (am  > 0.5f ? (am  - 0.5f) / 0.5f : 0.f);
    float p_bod = bod < 0.001f ? (0.001f - bod) / 0.001f: (bod > 5.0f ? (bod - 5.0f) / 5.0f : 0.f);
    float p_do  = dox < 6.0f   ? (6.0f - dox) / 6.0f    : 0.f;
    float p_ni  = ni  < 0.001f ? (0.001f - ni) / 0.001f : (ni  > 10.f ? (ni  - 10.f) / 10.f : 0.f);

    float bact = (1.2f * am / 0.5f + 1.5f * bod / 5.0f - 0.8f * dox / 10.0f) * (1.f / 3.f);
    float chem = (1.5f * ph / 8.5f + ni / 10.0f) * 0.5f;
    float org  = (2.0f * bod / 5.0f - 1.5f * dox / 10.0f + 0.8f * am / 0.5f) * (1.f / 3.f);
    float agri = 2.0f * ni / 10.0f;
    float comp = 1.f / (1.f + (p_ph + p_am + p_bod + p_do + p_ni) + 1e-8f);

    float f[10] = { p_ph, p_am, p_bod, p_do, p_ni, bact, chem, org, agri, comp };
    float* hr = g_h + i * 64;
#pragma unroll
    for (int k = 0; k < 16; k++) hr[k] = xr[k];
    for (int j = 0; j < 32; j++) {
        float s = symb[j];
#pragma unroll
        for (int k = 0; k < 10; k++) s += f[k] * symW[j * 10 + k];
        hr[16 + j] = eluf(s);
    }
}

// one warp per row: bitmap -> canonical uint16 list in gmem, then RE-ZERO the
// bitmap row (restores the all-zero invariant for the next graph replay).
__global__ void k_build() {
    int warp = threadIdx.x >> 5;
    int lane = threadIdx.x & 31;
    int i = blockIdx.x * 8 + warp;

    unsigned* fw = g_bf + (i << 8);
    unsigned* rv = g_br + (i << 8);
    unsigned short* dst = g_nbr + i * LISTCAP;
    int total = 0;
    for (int it = 0; it < 8; it++) {
        int wi = it * 32 + lane;
        unsigned f = fw[wi];
        unsigned r = rv[wi];
        unsigned u = f | r;
        int cnt = __popc(u);
        int pre = cnt;
#pragma unroll
        for (int o = 1; o < 32; o <<= 1) {
            int t = __shfl_up_sync(0xffffffffu, pre, o);
            if (lane >= o) pre += t;
        }
        int wtot = __shfl_sync(0xffffffffu, pre, 31);
        int pos = total + pre - cnt;
        while (u) {
            int b = __ffs(u) - 1;
            u &= u - 1;
            unsigned F = (f >> b) & 1;
            unsigned R = (r >> b) & 1;
            if (pos < LISTCAP)
                dst[pos] = (unsigned short)((wi * 32 + b) | (F << 13) | (R << 14));
            pos++;
        }
        total += wtot;
        fw[wi] = 0u;           // restore zero invariant
        rv[wi] = 0u;
    }
    if (total > LISTCAP) total = LISTCAP;
    if (lane == 0) g_cnt[i] = total;
}

// Fused: ht = h[:, :K] @ W^T (fp32 + fp16 shadow); asrc/adst; column partials.
__global__ void k_gemm_fused(const float* __restrict__ W,
                             const float* __restrict__ att, int K) {
    __shared__ __align__(16) float Ws[64][68];
    __shared__ float As[64][65];
    __shared__ float sAtt[128];
    __shared__ float spart[8][64];

    int tid = threadIdx.x;
    int rowBase = blockIdx.x * 64;

    if (blockIdx.x == 0 && tid == 0) g_fillbits = 0u;   // reset for this layer

    for (int idx = tid; idx < 64 * K; idx += 256) {
        int c = idx / K, k = idx % K;
        Ws[k][c] = W[idx];
    }
    for (int idx = tid; idx < 64 * K; idx += 256) {
        int r = idx / K, k = idx % K;
        As[r][k] = g_h[(rowBase + r) * 64 + k];
    }
    if (tid < 128) sAtt[tid] = att[tid];
    __syncthreads();

    int cg = tid & 7;
    int rg = tid >> 3;
    int r0 = rg * 2;
    int c0 = cg * 8;

    float acc0[8] = {}, acc1[8] = {};
    for (int k = 0; k < K; k++) {
        float a0 = As[r0][k];
        float a1 = As[r0 + 1][k];
        float4 w0 = *(const float4*)&Ws[k][c0];
        float4 w1 = *(const float4*)&Ws[k][c0 + 4];
        acc0[0] += a0 * w0.x; acc0[1] += a0 * w0.y; acc0[2] += a0 * w0.z; acc0[3] += a0 * w0.w;
        acc0[4] += a0 * w1.x; acc0[5] += a0 * w1.y; acc0[6] += a0 * w1.z; acc0[7] += a0 * w1.w;
        acc1[0] += a1 * w0.x; acc1[1] += a1 * w0.y; acc1[2] += a1 * w0.z; acc1[3] += a1 * w0.w;
        acc1[4] += a1 * w1.x; acc1[5] += a1 * w1.y; acc1[6] += a1 * w1.z; acc1[7] += a1 * w1.w;
    }

    int R0 = rowBase + r0;
    float4* hp0 = (float4*)(g_ht + R0 * 64 + c0);
    float4* hp1 = (float4*)(g_ht + (R0 + 1) * 64 + c0);
    hp0[0] = make_float4(acc0[0], acc0[1], acc0[2], acc0[3]);
    hp0[1] = make_float4(acc0[4], acc0[5], acc0[6], acc0[7]);
    hp1[0] = make_float4(acc1[0], acc1[1], acc1[2], acc1[3]);
    hp1[1] = make_float4(acc1[4], acc1[5], acc1[6], acc1[7]);

    // fp16 shadow (16 B per row-half)
    *(uint4*)(g_hth + R0 * 64 + c0) = make_uint4(
        h2u(__floats2half2_rn(acc0[0], acc0[1])),
        h2u(__floats2half2_rn(acc0[2], acc0[3])),
        h2u(__floats2half2_rn(acc0[4], acc0[5])),
        h2u(__floats2half2_rn(acc0[6], acc0[7])));
    *(uint4*)(g_hth + (R0 + 1) * 64 + c0) = make_uint4(
        h2u(__floats2half2_rn(acc1[0], acc1[1])),
        h2u(__floats2half2_rn(acc1[2], acc1[3])),
        h2u(__floats2half2_rn(acc1[4], acc1[5])),
        h2u(__floats2half2_rn(acc1[6], acc1[7])));

    float s0 = 0.f, d0 = 0.f, s1 = 0.f, d1 = 0.f;
#pragma unroll
    for (int m = 0; m < 8; m++) {
        float aw = sAtt[c0 + m], dw = sAtt[64 + c0 + m];
        s0 += acc0[m] * aw;  d0 += acc0[m] * dw;
        s1 += acc1[m] * aw;  d1 += acc1[m] * dw;
    }
#pragma unroll
    for (int o = 1; o < 8; o <<= 1) {
        s0 += __shfl_xor_sync(0xffffffffu, s0, o);
        d0 += __shfl_xor_sync(0xffffffffu, d0, o);
        s1 += __shfl_xor_sync(0xffffffffu, s1, o);
        d1 += __shfl_xor_sync(0xffffffffu, d1, o);
    }
    if (cg == 0) {
        g_asrc[R0] = s0;  g_adst[R0] = d0;
        g_asrc[R0 + 1] = s1;  g_adst[R0 + 1] = d1;
    }

    int lane = tid & 31, warp = tid >> 5;
    float colv[8];
#pragma unroll
    for (int m = 0; m < 8; m++) {
        float v = acc0[m] + acc1[m];
        v += __shfl_xor_sync(0xffffffffu, v, 8);
        v += __shfl_xor_sync(0xffffffffu, v, 16);
        colv[m] = v;
    }
    if (lane < 8) {
#pragma unroll
        for (int m = 0; m < 8; m++) spart[warp][lane * 8 + m] = colv[m];
    }
    __syncthreads();
    if (tid < 64) {
        float s = 0.f;
#pragma unroll
        for (int w = 0; w < 8; w++) s += spart[w][tid];
        g_part[blockIdx.x * 64 + tid] = s;
    }
}

// edge-max (fill) + Ssum reduction (block 0). grid = EM_BLOCKS(512) x 256.
__global__ void k_edge_max(const int* __restrict__ ei) {
    __shared__ float wmax[8];
    if (blockIdx.x == 0) {
        __shared__ float red[256];
        int t = threadIdx.x;
        int col = t & 63, q = t >> 6;
        float s = 0.f;
        for (int b = q; b < GEMM_BLOCKS; b += 4) s += g_part[b * 64 + col];
        red[t] = s;
        __syncthreads();
        if (t < 64) g_Ssum[t] = red[t] + red[64 + t] + red[128 + t] + red[192 + t];
    }
    int k0 = (blockIdx.x * 256 + threadIdx.x) * 2;   // covers E exactly
    int2 r2 = *(const int2*)(ei + k0);
    int2 c2 = *(const int2*)(ei + E + k0);
    float NEG = -3.0e38f;
    float a0 = ((unsigned)r2.x < N) ? g_asrc[r2.x] : NEG;
    float a1 = ((unsigned)r2.y < N) ? g_asrc[r2.y] : NEG;
    float b0 = ((unsigned)c2.x < N) ? g_adst[c2.x] : NEG;
    float b1 = ((unsigned)c2.y < N) ? g_adst[c2.y] : NEG;
    float m = fmaxf(a0 + b0, a1 + b1);
#pragma unroll
    for (int o = 16; o; o >>= 1) m = fmaxf(m, __shfl_xor_sync(0xffffffffu, m, o));
    int warp = threadIdx.x >> 5;
    if ((threadIdx.x & 31) == 0) wmax[warp] = m;
    __syncthreads();
    if (threadIdx.x == 0) {
        float bm = wmax[0];
#pragma unroll
        for (int w = 1; w < 8; w++) bm = fmaxf(bm, wmax[w]);
        atomicMax(&g_fillbits, fmap(lrelu(bm)));    // lrelu monotone
    }
}

// Shared aggregation core (fp16 neighbor gathers; fp32 weights/self/Ssum).
__device__ __forceinline__ void agg_core(int i, int warp, int lane,
                                         unsigned short (*list)[LISTCAP],
                                         float (*wbuf)[LISTCAP],
                                         float& o0, float& o1) {
    int total = g_cnt[i];
    const unsigned* src = (const unsigned*)(g_nbr + i * LISTCAP);
    unsigned* dstw = (unsigned*)&list[warp][0];
    for (int t = lane; t * 2 < total; t += 32) dstw[t] = src[t];
    __syncwarp();

    float fill = funmap(g_fillbits);
    float enf = expf(-fill);
    float ai = g_asrc[i];
    float di = g_adst[i];
    float z = 0.f;
    for (int n = lane; n < total; n += 32) {
        unsigned ent = list[warp][n];
        int j = ent & 8191;
        float aj = g_asrc[j];
        float dj = g_adst[j];
        float e1 = (ent & (1u << 13)) ? lrelu(ai + dj) : 0.f;
        float e2 = (ent & (1u << 14)) ? lrelu(aj + di) : 0.f;
        float w = expf(0.5f * (e1 + e2) - fill) - enf;
        wbuf[warp][n] = w;
        z += w;
    }
#pragma unroll
    for (int o = 16; o; o >>= 1) z += __shfl_xor_sync(0xffffffffu, z, o);
    __syncwarp();

    int c0 = lane * 2;
    float acc0 = 0.f, acc1 = 0.f;
    int n = 0;
    for (; n + 3 < total; n += 4) {
        float w0 = wbuf[warp][n],     w1 = wbuf[warp][n + 1];
        float w2 = wbuf[warp][n + 2], w3 = wbuf[warp][n + 3];
        int j0 = list[warp][n] & 8191,     j1 = list[warp][n + 1] & 8191;
        int j2 = list[warp][n + 2] & 8191, j3 = list[warp][n + 3] & 8191;
        float2 h0 = __half22float2(*(const __half2*)(g_hth + j0 * 64 + c0));
        float2 h1 = __half22float2(*(const __half2*)(g_hth + j1 * 64 + c0));
        float2 h2 = __half22float2(*(const __half2*)(g_hth + j2 * 64 + c0));
        float2 h3 = __half22float2(*(const __half2*)(g_hth + j3 * 64 + c0));
        acc0 += w0 * h0.x + w1 * h1.x + w2 * h2.x + w3 * h3.x;
        acc1 += w0 * h0.y + w1 * h1.y + w2 * h2.y + w3 * h3.y;
    }
    for (; n < total; n++) {
        float w0 = wbuf[warp][n];
        int j0 = list[warp][n] & 8191;
        float2 h0 = __half22float2(*(const __half2*)(g_hth + j0 * 64 + c0));
        acc0 += w0 * h0.x;
        acc1 += w0 * h0.y;
    }

    float Z = 1.f + 8191.f * enf + z;
    float hi0 = g_ht[i * 64 + c0];
    float hi1 = g_ht[i * 64 + c0 + 1];
    float r0 = (acc0 + enf * g_Ssum[c0]     + (1.f - enf) * hi0) / Z;
    float r1 = (acc1 + enf * g_Ssum[c0 + 1] + (1.f - enf) * hi1) / Z;
    o0 = eluf(r0);
    o1 = eluf(r1);
}

// layers 0/1: lean smem
__global__ void k_agg(int residual) {
    __shared__ unsigned short list[8][LISTCAP];
    __shared__ float wbuf[8][LISTCAP];
    int warp = threadIdx.x >> 5;
    int lane = threadIdx.x & 31;
    int i = blockIdx.x * 8 + warp;
    int c0 = lane * 2;

    float o0, o1;
    agg_core(i, warp, lane, list, wbuf, o0, o1);

    if (residual) {
        g_h[i * 64 + c0]     += o0;
        g_h[i * 64 + c0 + 1] += o1;
    } else {
        g_h[i * 64 + c0]     = o0;
        g_h[i * 64 + c0 + 1] = o1;
    }
}

// layer 2: aggregation + residual + both head MLPs + output writes
__global__ void k_agg_heads(const float* __restrict__ rW1, const float* __restrict__ rb1,
                            const float* __restrict__ rW2, const float* __restrict__ rb2,
                            const float* __restrict__ cW1, const float* __restrict__ cb1,
                            const float* __restrict__ cW2, const float* __restrict__ cb2,
                            float* __restrict__ out) {
    __shared__ unsigned short list[8][LISTCAP];
    __shared__ float wbuf[8][LISTCAP];
    __shared__ float sRW1[32][65];
    __shared__ float sCW1[32][65];
    __shared__ float sRW2[32];
    __shared__ float sCW2[128];
    __shared__ float sRb1[32];
    __shared__ float sCb1[32];
    __shared__ float srow[8][64];

    int tid = threadIdx.x;
    int warp = tid >> 5;
    int lane = tid & 31;
    int i = blockIdx.x * 8 + warp;
    int c0 = lane * 2;

    for (int idx = tid; idx < 2048; idx += 256) {
        sRW1[idx >> 6][idx & 63] = rW1[idx];
        sCW1[idx >> 6][idx & 63] = cW1[idx];
    }
    if (tid < 32) { sRW2[tid] = rW2[tid]; sRb1[tid] = rb1[tid]; sCb1[tid] = cb1[tid]; }
    if (tid < 128) sCW2[tid] = cW2[tid];
    __syncthreads();

    float o0, o1;
    agg_core(i, warp, lane, list, wbuf, o0, o1);

    float h0 = g_h[i * 64 + c0]     + o0;
    float h1 = g_h[i * 64 + c0 + 1] + o1;
    srow[warp][c0]     = h0;
    srow[warp][c0 + 1] = h1;
    __syncwarp();

    float t1 = sRb1[lane];
    float t2 = sCb1[lane];
#pragma unroll
    for (int k = 0; k < 64; k++) {
        float hv = srow[warp][k];
        t1 += hv * sRW1[lane][k];
        t2 += hv * sCW1[lane][k];
    }
    t1 = eluf(t1);
    t2 = eluf(t2);

    float p = t1 * sRW2[lane];
#pragma unroll
    for (int o = 16; o; o >>= 1) p += __shfl_xor_sync(0xffffffffu, p, o);
    if (lane == 0) out[i] = p + rb2[0];

#pragma unroll
    for (int k = 0; k < 4; k++) {
        float q = t2 * sCW2[k * 32 + lane];
#pragma unroll
        for (int o = 16; o; o >>= 1) q += __shfl_xor_sync(0xffffffffu, q, o);
        if (lane == 0) out[N + i * 4 + k] = q + cb2[k];
    }

    ((float2*)(out + N + 4 * N))[i * 32 + lane] = make_float2(h0, h1);
}

// ---------------- launch ----------------
extern "C" void kernel_launch(void* const* d_in, const int* in_sizes, int n_in,
                              void* d_out, int out_size) {
    const float* x    = (const float*)d_in[0];
    const int*   ei   = (const int*)d_in[1];   // int32 (JAX downcast)
    const float* symW = (const float*)d_in[3];
    const float* symb = (const float*)d_in[4];
    const float* W0   = (const float*)d_in[5];
    const float* att0 = (const float*)d_in[6];
    const float* W1   = (const float*)d_in[7];
    const float* att1 = (const float*)d_in[8];
    const float* W2   = (const float*)d_in[9];
    const float* att2 = (const float*)d_in[10];
    const float* rW1  = (const float*)d_in[11];
    const float* rb1  = (const float*)d_in[12];
    const float* rW2  = (const float*)d_in[13];
    const float* rb2  = (const float*)d_in[14];
    const float* cW1  = (const float*)d_in[15];
    const float* cb1  = (const float*)d_in[16];
    const float* cW2  = (const float*)d_in[17];
    const float* cb2  = (const float*)d_in[18];
    float* out = (float*)d_out;

    k_setbits_feat<<<SB_BLOCKS, 256>>>(ei, x, symW, symb);
    k_build<<<1024, 256>>>();

    const float* Ws[3]   = { W0, W1, W2 };
    const float* atts[3] = { att0, att1, att2 };
    int Kd[3] = { 48, 64, 64 };
    for (int L = 0; L < 3; L++) {
        k_gemm_fused<<<GEMM_BLOCKS, 256>>>(Ws[L], atts[L], Kd[L]);
        k_edge_max<<<EM_BLOCKS, 256>>>(ei);
        if (L < 2) {
            k_agg<<<1024, 256>>>(L);
        } else {
            k_agg_heads<<<1024, 256>>>(rW1, rb1, rW2, rb2, cW1, cb1, cW2, cb2, out);
        }
    }
}